// round 12
// baseline (speedup 1.0000x reference)
#include <cuda_runtime.h>
#include <math.h>
#include <stdint.h>

#define Bsz   8192
#define DIN   1024
#define Hdim  128
#define Ecnt  8
#define DOUT  1024
#define BKSEL 2048   // ceil(K*B/E) = ceil(2*8192/8)

// ---------------- scratch (device globals; no runtime allocation) ----------
__device__ float g_logits[Bsz * Ecnt];
__device__ int   g_idx[Ecnt][BKSEL];
__device__ float g_nws[Ecnt][BKSEL];
__device__ int   g_sel_slot[Bsz][Ecnt];
__device__ float g_eo[(size_t)BKSEL * Ecnt * DOUT]; // 64 MB [slot][e][d]
__device__ float g_xt[(size_t)Bsz * DIN];           // x, tf32-rounded (by router)
__device__ float g_wt[(size_t)Ecnt * DIN * DOUT];   // we [e][k][n], tf32-rounded

// ---------------------------------------------------------------------------
// helpers
// ---------------------------------------------------------------------------
__device__ __forceinline__ void cp_async16(void* smem, const void* gmem) {
    uint32_t s = (uint32_t)__cvta_generic_to_shared(smem);
    asm volatile("cp.async.cg.shared.global [%0], [%1], 16;\n" :: "r"(s), "l"(gmem));
}
__device__ __forceinline__ uint32_t f2tf32(float v) {
    uint32_t r;
    asm("cvt.rna.tf32.f32 %0, %1;\n" : "=r"(r) : "f"(v));
    return r;
}
__device__ __forceinline__ void mma_tf32(float* cc,
                                         const uint32_t* a, const uint32_t* b) {
    asm volatile(
        "mma.sync.aligned.m16n8k8.row.col.f32.tf32.tf32.f32 "
        "{%0,%1,%2,%3}, {%4,%5,%6,%7}, {%8,%9}, {%0,%1,%2,%3};\n"
        : "+f"(cc[0]), "+f"(cc[1]), "+f"(cc[2]), "+f"(cc[3])
        : "r"(a[0]), "r"(a[1]), "r"(a[2]), "r"(a[3]), "r"(b[0]), "r"(b[1]));
}
// packed dual-fp32 FMA (Blackwell FFMA2). Per-lane IEEE fp32 fma.
__device__ __forceinline__ void fma_x2(uint64_t& acc, uint64_t a, uint64_t b) {
    asm("fma.rn.f32x2 %0, %1, %2, %0;" : "+l"(acc) : "l"(a), "l"(b));
}
__device__ __forceinline__ uint64_t splat_x2(float v) {
    uint64_t r;
    uint32_t u = __float_as_uint(v);
    asm("mov.b64 %0, {%1, %1};" : "=l"(r) : "r"(u));
    return r;
}

// ---------------------------------------------------------------------------
// Kernel 0: we -> g_wt (tf32-rounded, same layout [e][k][n])
// ---------------------------------------------------------------------------
__global__ __launch_bounds__(256) void k_cvtw(const float* __restrict__ we)
{
    const size_t n = (size_t)Ecnt * DIN * DOUT / 4;
    for (size_t i = (size_t)blockIdx.x * blockDim.x + threadIdx.x; i < n;
         i += (size_t)gridDim.x * blockDim.x) {
        float4 v = ((const float4*)we)[i];
        v.x = __uint_as_float(f2tf32(v.x));
        v.y = __uint_as_float(f2tf32(v.y));
        v.z = __uint_as_float(f2tf32(v.z));
        v.w = __uint_as_float(f2tf32(v.w));
        ((float4*)g_wt)[i] = v;
    }
}

// ---------------------------------------------------------------------------
// Kernel 1: router fused — h = relu((x@w1+b1) * relu(x@wg+bg)) staged in smem,
// then logits = h @ w2 + b2 in the epilogue. Full fp32 via packed FFMA2.
// Also emits g_xt = tf32-rounded x.
// ---------------------------------------------------------------------------
__global__ __launch_bounds__(256) void k_router(
    const float* __restrict__ x,
    const float* __restrict__ w1, const float* __restrict__ b1,
    const float* __restrict__ wg, const float* __restrict__ bg,
    const float* __restrict__ w2, const float* __restrict__ b2)
{
    __shared__ float Xs[16][64];
    __shared__ float W1s[16][128];
    __shared__ float WGs[16][128];
    __shared__ float Hs[64][132];
    __shared__ float W2s[Hdim * Ecnt];

    const int tid = threadIdx.x;
    const int tx  = tid & 31;
    const int ty  = tid >> 5;
    const int row0 = blockIdx.x * 64;

    uint64_t acc1p[8][2];
    uint64_t accgp[8][2];
#pragma unroll
    for (int i = 0; i < 8; i++)
#pragma unroll
        for (int j2 = 0; j2 < 2; j2++) { acc1p[i][j2] = 0ull; accgp[i][j2] = 0ull; }

    for (int k0 = 0; k0 < DIN; k0 += 16) {
        {
            int m  = tid >> 2;
            int kq = (tid & 3) << 2;
            float4 v = *(const float4*)(x + (size_t)(row0 + m) * DIN + k0 + kq);
            Xs[kq + 0][m] = v.x; Xs[kq + 1][m] = v.y;
            Xs[kq + 2][m] = v.z; Xs[kq + 3][m] = v.w;
            float4 vr;
            vr.x = __uint_as_float(f2tf32(v.x));
            vr.y = __uint_as_float(f2tf32(v.y));
            vr.z = __uint_as_float(f2tf32(v.z));
            vr.w = __uint_as_float(f2tf32(v.w));
            *(float4*)(g_xt + (size_t)(row0 + m) * DIN + k0 + kq) = vr;
        }
#pragma unroll
        for (int r = 0; r < 2; r++) {
            int lin = tid + r * 256;
            int kk  = lin >> 5;
            int nq  = (lin & 31) << 2;
            *(float4*)&W1s[kk][nq] = *(const float4*)(w1 + (size_t)(k0 + kk) * Hdim + nq);
            *(float4*)&WGs[kk][nq] = *(const float4*)(wg + (size_t)(k0 + kk) * Hdim + nq);
        }
        __syncthreads();
#pragma unroll
        for (int kk = 0; kk < 16; kk++) {
            uint64_t xp[8];
#pragma unroll
            for (int i = 0; i < 8; i++) xp[i] = splat_x2(Xs[kk][i * 8 + ty]);
            uint64_t w1p[2], wgp[2];
#pragma unroll
            for (int j2 = 0; j2 < 2; j2++) {
                w1p[j2] = *(const uint64_t*)&W1s[kk][j2 * 64 + 2 * tx];
                wgp[j2] = *(const uint64_t*)&WGs[kk][j2 * 64 + 2 * tx];
            }
#pragma unroll
            for (int i = 0; i < 8; i++)
#pragma unroll
                for (int j2 = 0; j2 < 2; j2++) {
                    fma_x2(acc1p[i][j2], xp[i], w1p[j2]);
                    fma_x2(accgp[i][j2], xp[i], wgp[j2]);
                }
        }
        __syncthreads();
    }

#pragma unroll
    for (int i = 0; i < 8; i++) {
        int r = i * 8 + ty;
#pragma unroll
        for (int j2 = 0; j2 < 2; j2++) {
            int n = j2 * 64 + 2 * tx;
            uint32_t alo, ahi, glo, ghi;
            asm("mov.b64 {%0, %1}, %2;" : "=r"(alo), "=r"(ahi) : "l"(acc1p[i][j2]));
            asm("mov.b64 {%0, %1}, %2;" : "=r"(glo), "=r"(ghi) : "l"(accgp[i][j2]));
            float a0 = __uint_as_float(alo) + b1[n];
            float a1 = __uint_as_float(ahi) + b1[n + 1];
            float g0 = fmaxf(__uint_as_float(glo) + bg[n],     0.f);
            float g1 = fmaxf(__uint_as_float(ghi) + bg[n + 1], 0.f);
            float2 hv;
            hv.x = fmaxf(a0 * g0, 0.f);
            hv.y = fmaxf(a1 * g1, 0.f);
            *(float2*)&Hs[r][n] = hv;
        }
    }
    for (int i = tid; i < Hdim * Ecnt; i += 256) W2s[i] = w2[i];
    __syncthreads();

    {
        const int r = tid >> 2;
        const int q = tid & 3;
        float acc[Ecnt];
#pragma unroll
        for (int e = 0; e < Ecnt; e++) acc[e] = 0.f;
#pragma unroll 4
        for (int k = 0; k < 32; k++) {
            int n = q * 32 + k;
            float hv = Hs[r][n];
#pragma unroll
            for (int e = 0; e < Ecnt; e++)
                acc[e] = fmaf(hv, W2s[n * Ecnt + e], acc[e]);
        }
#pragma unroll
        for (int e = 0; e < Ecnt; e++) {
            acc[e] += __shfl_xor_sync(0xffffffffu, acc[e], 1);
            acc[e] += __shfl_xor_sync(0xffffffffu, acc[e], 2);
        }
        if (q == 0) {
#pragma unroll
            for (int e = 0; e < Ecnt; e++)
                g_logits[(size_t)(row0 + r) * Ecnt + e] = acc[e] + b2[e];
        }
    }
}

// ---------------------------------------------------------------------------
// Kernel 3: per expert — column softmax, exact top-2048 (radix bisection).
// ---------------------------------------------------------------------------
#define EQ_CAP 1024
__global__ __launch_bounds__(1024) void k_select()
{
    __shared__ float lv[Bsz];
    __shared__ float s_warp[32];
    __shared__ int   s_bits[32];
    __shared__ unsigned s_cnt;
    __shared__ int   s_eq[EQ_CAP];
    __shared__ unsigned s_eqn;
    __shared__ float s_bf;

    const int e    = blockIdx.x;
    const int tid  = threadIdx.x;
    const int lane = tid & 31;
    const int wid  = tid >> 5;

    float loc[8];
#pragma unroll
    for (int r = 0; r < 8; r++) {
        int i = tid * 8 + r;
        loc[r] = g_logits[(size_t)i * Ecnt + e];
        g_sel_slot[i][e] = -1;
    }
    if (tid < 32) s_bits[tid] = 0;
    if (tid == 0) { s_cnt = 0u; s_eqn = 0u; }

    float m = loc[0];
#pragma unroll
    for (int r = 1; r < 8; r++) m = fmaxf(m, loc[r]);
#pragma unroll
    for (int o = 16; o > 0; o >>= 1) m = fmaxf(m, __shfl_xor_sync(0xffffffffu, m, o));
    if (lane == 0) s_warp[wid] = m;
    __syncthreads();
    if (tid < 32) {
        float v = s_warp[tid];
#pragma unroll
        for (int o = 16; o > 0; o >>= 1) v = fmaxf(v, __shfl_xor_sync(0xffffffffu, v, o));
        if (tid == 0) s_bf = v;
    }
    __syncthreads();
    m = s_bf;
    __syncthreads();

    float s = 0.f;
#pragma unroll
    for (int r = 0; r < 8; r++) s += expf(loc[r] - m);
#pragma unroll
    for (int o = 16; o > 0; o >>= 1) s += __shfl_xor_sync(0xffffffffu, s, o);
    if (lane == 0) s_warp[wid] = s;
    __syncthreads();
    if (tid < 32) {
        float v = s_warp[tid];
#pragma unroll
        for (int o = 16; o > 0; o >>= 1) v += __shfl_xor_sync(0xffffffffu, v, o);
        if (tid == 0) s_bf = v;
    }
    __syncthreads();
    s = s_bf;
    __syncthreads();

    const float inv_s = 1.0f / s;
    unsigned ub[8];
#pragma unroll
    for (int r = 0; r < 8; r++) {
        float v = expf(loc[r] - m) * inv_s;
        lv[tid * 8 + r] = v;
        ub[r] = __float_as_uint(v);
    }
    __syncthreads();

    unsigned cur = 0u;
    for (int bit = 29; bit >= 0; bit--) {
        unsigned cand = cur | (1u << bit);
        int c = 0;
#pragma unroll
        for (int r = 0; r < 8; r++) c += (ub[r] >= cand) ? 1 : 0;
#pragma unroll
        for (int o = 16; o > 0; o >>= 1) c += __shfl_xor_sync(0xffffffffu, c, o);
        if (lane == 0) atomicAdd(&s_bits[bit], c);
        __syncthreads();
        if (s_bits[bit] >= BKSEL) cur = cand;
    }
    const unsigned V = cur;

#pragma unroll
    for (int r = 0; r < 8; r++) {
        int i = tid * 8 + r;
        if (ub[r] > V) {
            unsigned p = atomicAdd(&s_cnt, 1u);
            g_idx[e][p] = i;
            g_sel_slot[i][e] = (int)p;
        } else if (ub[r] == V) {
            unsigned q = atomicAdd(&s_eqn, 1u);
            if (q < EQ_CAP) s_eq[q] = i;
        }
    }
    __syncthreads();

    const unsigned n_greater = s_cnt;
    const unsigned needed    = BKSEL - n_greater;
    const unsigned eqn       = s_eqn;

    if (eqn == needed && eqn <= EQ_CAP) {
        for (unsigned q = tid; q < eqn; q += 1024) {
            int i = s_eq[q];
            unsigned p = n_greater + q;
            g_idx[e][p] = i;
            g_sel_slot[i][e] = (int)p;
        }
    } else if (tid == 0) {
        unsigned p = n_greater;
        for (int i = 0; i < Bsz && p < BKSEL; i++) {
            if (__float_as_uint(lv[i]) == V) {
                g_idx[e][p] = i;
                g_sel_slot[i][e] = (int)p;
                p++;
            }
        }
    }
    __syncthreads();

    float wsv[2];
    float m2 = -1e30f;
#pragma unroll
    for (int r = 0; r < 2; r++) {
        int slot = tid + r * 1024;
        wsv[r] = lv[g_idx[e][slot]];
        m2 = fmaxf(m2, wsv[r]);
    }
#pragma unroll
    for (int o = 16; o > 0; o >>= 1) m2 = fmaxf(m2, __shfl_xor_sync(0xffffffffu, m2, o));
    if (lane == 0) s_warp[wid] = m2;
    __syncthreads();
    if (tid < 32) {
        float v = s_warp[tid];
#pragma unroll
        for (int o = 16; o > 0; o >>= 1) v = fmaxf(v, __shfl_xor_sync(0xffffffffu, v, o));
        if (tid == 0) s_bf = v;
    }
    __syncthreads();
    m2 = s_bf;
    __syncthreads();

    float s2 = expf(wsv[0] - m2) + expf(wsv[1] - m2);
#pragma unroll
    for (int o = 16; o > 0; o >>= 1) s2 += __shfl_xor_sync(0xffffffffu, s2, o);
    if (lane == 0) s_warp[wid] = s2;
    __syncthreads();
    if (tid < 32) {
        float v = s_warp[tid];
#pragma unroll
        for (int o = 16; o > 0; o >>= 1) v += __shfl_xor_sync(0xffffffffu, v, o);
        if (tid == 0) s_bf = v;
    }
    __syncthreads();
    s2 = s_bf;

    const float inv_s2 = 1.0f / s2;
#pragma unroll
    for (int r = 0; r < 2; r++)
        g_nws[e][tid + r * 1024] = expf(wsv[r] - m2) * inv_s2;
}

// ---------------------------------------------------------------------------
// Kernel 4: expert GEMM (tf32 mma.sync m16n8k8), re-tiled for issue balance:
// block tile 128m x 256n, 8 warps (2m x 4n), warp tile 64x64 = 4x8 subtiles.
// Per k8-step: 32 LDS.32 vs 32 MMAs (was 24 vs 16). 3-stage cp.async ring,
// one __syncthreads per kb16. Dynamic smem (81 KB), 1 CTA/SM.
// ---------------------------------------------------------------------------
#define A_STRIDE 20
#define B_STRIDE 264
#define A_STG (128 * A_STRIDE)          // floats per A stage
#define B_STG (16 * B_STRIDE)           // floats per B stage
#define SMEM_EXPERT_BYTES ((3 * (A_STG + B_STG)) * 4)

__global__ __launch_bounds__(256, 1) void k_expert(
    const float* __restrict__ be)
{
    extern __shared__ float smem[];
    float* As = smem;                    // [3][128][A_STRIDE]
    float* Bs = smem + 3 * A_STG;        // [3][16][B_STRIDE]
    __shared__ int ridx[128];

    const int e  = blockIdx.z;
    const int m0 = blockIdx.y * 128;
    const int n0 = blockIdx.x * 256;
    const int tid  = threadIdx.x;
    const int lane = tid & 31;
    const int w    = tid >> 5;
    const int wm   = w & 1;        // warp row (0..1) -> 64 rows
    const int wn   = w >> 1;       // warp col (0..3) -> 64 cols
    const int g    = lane >> 2;    // group id 0..7
    const int c    = lane & 3;     // thread-in-group 0..3

    if (tid < 128) ridx[tid] = g_idx[e][m0 + tid];
    __syncthreads();

    const float* weE = g_wt + (size_t)e * DIN * DOUT + n0;

    float acc[4][8][4];
#pragma unroll
    for (int mi = 0; mi < 4; mi++)
#pragma unroll
        for (int nj = 0; nj < 8; nj++)
#pragma unroll
            for (int q = 0; q < 4; q++) acc[mi][nj][q] = 0.f;

    // A tile: 128x16 = 512 f4 -> 2/thread.  B tile: 16x256 = 1024 f4 -> 4/thread.
#define LOAD_STAGE(buf, k0)                                                    \
    do {                                                                       \
        float* A_ = As + (buf) * A_STG;                                        \
        float* B_ = Bs + (buf) * B_STG;                                        \
        _Pragma("unroll")                                                      \
        for (int s_ = 0; s_ < 2; s_++) {                                       \
            int lin = tid + s_ * 256;                                          \
            int row = lin >> 2, col = (lin & 3) << 2;                          \
            cp_async16(A_ + row * A_STRIDE + col,                              \
                       g_xt + (size_t)ridx[row] * DIN + (k0) + col);           \
        }                                                                      \
        _Pragma("unroll")                                                      \
        for (int s_ = 0; s_ < 4; s_++) {                                       \
            int lin = tid + s_ * 256;                                          \
            int kk_ = lin >> 6, nq = (lin & 63) << 2;                          \
            cp_async16(B_ + kk_ * B_STRIDE + nq,                               \
                       weE + (size_t)((k0) + kk_) * DOUT + nq);                \
        }                                                                      \
        asm volatile("cp.async.commit_group;\n");                              \
    } while (0)

    LOAD_STAGE(0, 0);
    LOAD_STAGE(1, 16);

    const int NT = DIN / 16;   // 64 iterations
    int buf = 0, nbuf = 2;
    for (int t = 0; t < NT; t++) {
        if (t + 2 < NT) {
            asm volatile("cp.async.wait_group 1;\n");
            __syncthreads();
            LOAD_STAGE(nbuf, (t + 2) * 16);
        } else {
            asm volatile("cp.async.wait_group 0;\n");
            __syncthreads();
        }

        const float* A_ = As + buf * A_STG;
        const float* B_ = Bs + buf * B_STG;
#pragma unroll
        for (int kk = 0; kk < 2; kk++) {        // two k8 steps per kb16
            uint32_t aF[4][4];
            uint32_t bF[8][2];
            const int kb8 = kk * 8;
#pragma unroll
            for (int mi = 0; mi < 4; mi++) {
                int row = wm * 64 + mi * 16 + g;
                aF[mi][0] = __float_as_uint(A_[ row      * A_STRIDE + kb8 + c    ]);
                aF[mi][1] = __float_as_uint(A_[(row + 8) * A_STRIDE + kb8 + c    ]);
                aF[mi][2] = __float_as_uint(A_[ row      * A_STRIDE + kb8 + c + 4]);
                aF[mi][3] = __float_as_uint(A_[(row + 8) * A_STRIDE + kb8 + c + 4]);
            }
#pragma unroll
            for (int nj = 0; nj < 8; nj++) {
                int nn = wn * 64 + nj * 8 + g;
                bF[nj][0] = __float_as_uint(B_[(kb8 + c    ) * B_STRIDE + nn]);
                bF[nj][1] = __float_as_uint(B_[(kb8 + c + 4) * B_STRIDE + nn]);
            }
#pragma unroll
            for (int mi = 0; mi < 4; mi++)
#pragma unroll
                for (int nj = 0; nj < 8; nj++)
                    mma_tf32(acc[mi][nj], aF[mi], bF[nj]);
        }
        buf++;  if (buf == 3)  buf = 0;
        nbuf++; if (nbuf == 3) nbuf = 0;
    }
#undef LOAD_STAGE

    const float* beE = be + (size_t)e * DOUT + n0;
#pragma unroll
    for (int mi = 0; mi < 4; mi++) {
        int slot0 = m0 + wm * 64 + mi * 16 + g;
        int slot1 = slot0 + 8;
        float nw0 = g_nws[e][slot0];
        float nw1 = g_nws[e][slot1];
        float* o0 = g_eo + ((size_t)slot0 * Ecnt + e) * DOUT + n0;
        float* o1 = g_eo + ((size_t)slot1 * Ecnt + e) * DOUT + n0;
#pragma unroll
        for (int nj = 0; nj < 8; nj++) {
            int n = wn * 64 + nj * 8 + c * 2;
            float bb0 = beE[n], bb1 = beE[n + 1];
            float2 v0, v1;
            v0.x = (acc[mi][nj][0] + bb0) * nw0;
            v0.y = (acc[mi][nj][1] + bb1) * nw0;
            v1.x = (acc[mi][nj][2] + bb0) * nw1;
            v1.y = (acc[mi][nj][3] + bb1) * nw1;
            *(float2*)(o0 + n) = v0;
            *(float2*)(o1 + n) = v1;
        }
    }
}

// ---------------------------------------------------------------------------
// Kernel 5: combine (float4). out[b, e*DOUT+d] = c_e[d] + sum_e' c_e'[d]
// ---------------------------------------------------------------------------
__global__ __launch_bounds__(256) void k_combine(float* __restrict__ out)
{
    __shared__ int slots[Ecnt];
    const int b   = blockIdx.x;
    const int tid = threadIdx.x;
    if (tid < Ecnt) slots[tid] = g_sel_slot[b][tid];
    __syncthreads();

    const int d = tid * 4;
    float4 cv[Ecnt];
    float4 ssum = make_float4(0.f, 0.f, 0.f, 0.f);
#pragma unroll
    for (int e = 0; e < Ecnt; e++) {
        int slot = slots[e];
        float4 v = make_float4(0.f, 0.f, 0.f, 0.f);
        if (slot >= 0)
            v = *(const float4*)(g_eo + ((size_t)slot * Ecnt + e) * DOUT + d);
        cv[e] = v;
        ssum.x += v.x; ssum.y += v.y; ssum.z += v.z; ssum.w += v.w;
    }
    float* orow = out + (size_t)b * (Ecnt * DOUT) + d;
#pragma unroll
    for (int e = 0; e < Ecnt; e++) {
        float4 o;
        o.x = cv[e].x + ssum.x;
        o.y = cv[e].y + ssum.y;
        o.z = cv[e].z + ssum.z;
        o.w = cv[e].w + ssum.w;
        *(float4*)(orow + (size_t)e * DOUT) = o;
    }
}

// ---------------------------------------------------------------------------
extern "C" void kernel_launch(void* const* d_in, const int* in_sizes, int n_in,
                              void* d_out, int out_size)
{
    const float* x  = (const float*)d_in[0];
    const float* w1 = (const float*)d_in[1];
    const float* b1 = (const float*)d_in[2];
    const float* wg = (const float*)d_in[3];
    const float* bg = (const float*)d_in[4];
    const float* w2 = (const float*)d_in[5];
    const float* b2 = (const float*)d_in[6];
    const float* we = (const float*)d_in[7];
    const float* be = (const float*)d_in[8];
    float* out = (float*)d_out;

    cudaFuncSetAttribute(k_expert, cudaFuncAttributeMaxDynamicSharedMemorySize,
                         SMEM_EXPERT_BYTES);

    k_cvtw<<<2048, 256>>>(we);
    k_router<<<Bsz / 64, 256>>>(x, w1, b1, wg, bg, w2, b2);
    k_select<<<Ecnt, 1024>>>();
    k_expert<<<dim3(DOUT / 256, BKSEL / 128, Ecnt), 256, SMEM_EXPERT_BYTES>>>(be);
    k_combine<<<Bsz, 256>>>(out);
}

// round 13
// speedup vs baseline: 1.1106x; 1.1106x over previous
#include <cuda_runtime.h>
#include <math.h>
#include <stdint.h>

#define Bsz   8192
#define DIN   1024
#define Hdim  128
#define Ecnt  8
#define DOUT  1024
#define BKSEL 2048   // ceil(K*B/E) = ceil(2*8192/8)

// ---------------- scratch (device globals; no runtime allocation) ----------
__device__ float g_logits[Bsz * Ecnt];
__device__ int   g_idx[Ecnt][BKSEL];
__device__ float g_nws[Ecnt][BKSEL];
__device__ int   g_sel_slot[Bsz][Ecnt];
__device__ float g_eo[(size_t)BKSEL * Ecnt * DOUT]; // 64 MB [slot][e][d]
__device__ float g_xt[(size_t)Bsz * DIN];           // x, tf32-rounded (by router)
__device__ float g_wt[(size_t)Ecnt * DOUT * DIN];   // we TRANSPOSED [e][n][k], tf32-rounded

// ---------------------------------------------------------------------------
// helpers
// ---------------------------------------------------------------------------
__device__ __forceinline__ void cp_async16_s(uint32_t smem, const void* gmem) {
    asm volatile("cp.async.cg.shared.global [%0], [%1], 16;\n" :: "r"(smem), "l"(gmem));
}
__device__ __forceinline__ uint32_t f2tf32(float v) {
    uint32_t r;
    asm("cvt.rna.tf32.f32 %0, %1;\n" : "=r"(r) : "f"(v));
    return r;
}
__device__ __forceinline__ void mma_tf32(float* cc,
                                         const uint32_t* a, const uint32_t* b) {
    asm volatile(
        "mma.sync.aligned.m16n8k8.row.col.f32.tf32.tf32.f32 "
        "{%0,%1,%2,%3}, {%4,%5,%6,%7}, {%8,%9}, {%0,%1,%2,%3};\n"
        : "+f"(cc[0]), "+f"(cc[1]), "+f"(cc[2]), "+f"(cc[3])
        : "r"(a[0]), "r"(a[1]), "r"(a[2]), "r"(a[3]), "r"(b[0]), "r"(b[1]));
}
__device__ __forceinline__ void ldsm_x4(uint32_t* r, uint32_t saddr) {
    asm volatile("ldmatrix.sync.aligned.m8n8.x4.shared.b16 {%0,%1,%2,%3}, [%4];"
                 : "=r"(r[0]), "=r"(r[1]), "=r"(r[2]), "=r"(r[3]) : "r"(saddr));
}
// packed dual-fp32 FMA (Blackwell FFMA2). Per-lane IEEE fp32 fma.
__device__ __forceinline__ void fma_x2(uint64_t& acc, uint64_t a, uint64_t b) {
    asm("fma.rn.f32x2 %0, %1, %2, %0;" : "+l"(acc) : "l"(a), "l"(b));
}
__device__ __forceinline__ uint64_t splat_x2(float v) {
    uint64_t r;
    uint32_t u = __float_as_uint(v);
    asm("mov.b64 %0, {%1, %1};" : "=l"(r) : "r"(u));
    return r;
}

// ---------------------------------------------------------------------------
// Kernel 0: we -> g_wt: transpose [e][k][n] -> [e][n][k] with tf32 rounding
// ---------------------------------------------------------------------------
__global__ __launch_bounds__(256) void k_cvtw(const float* __restrict__ we)
{
    __shared__ float tile[32][33];
    const int e  = blockIdx.z;
    const int k0 = blockIdx.y * 32;
    const int n0 = blockIdx.x * 32;
    const int tx = threadIdx.x & 31;
    const int ty = threadIdx.x >> 5;

    const float* src = we + ((size_t)e * DIN + k0) * DOUT + n0;
#pragma unroll
    for (int r = ty; r < 32; r += 8)
        tile[r][tx] = __uint_as_float(f2tf32(src[(size_t)r * DOUT + tx]));
    __syncthreads();
    float* dst = g_wt + ((size_t)e * DOUT + n0) * DIN + k0;
#pragma unroll
    for (int r = ty; r < 32; r += 8)
        dst[(size_t)r * DIN + tx] = tile[tx][r];
}

// ---------------------------------------------------------------------------
// Kernel 1: router fused — h = relu((x@w1+b1) * relu(x@wg+bg)) staged in smem,
// then logits = h @ w2 + b2 in the epilogue. Full fp32 via packed FFMA2.
// Also emits g_xt = tf32-rounded x.
// ---------------------------------------------------------------------------
__global__ __launch_bounds__(256) void k_router(
    const float* __restrict__ x,
    const float* __restrict__ w1, const float* __restrict__ b1,
    const float* __restrict__ wg, const float* __restrict__ bg,
    const float* __restrict__ w2, const float* __restrict__ b2)
{
    __shared__ float Xs[16][64];
    __shared__ float W1s[16][128];
    __shared__ float WGs[16][128];
    __shared__ float Hs[64][132];
    __shared__ float W2s[Hdim * Ecnt];

    const int tid = threadIdx.x;
    const int tx  = tid & 31;
    const int ty  = tid >> 5;
    const int row0 = blockIdx.x * 64;

    uint64_t acc1p[8][2];
    uint64_t accgp[8][2];
#pragma unroll
    for (int i = 0; i < 8; i++)
#pragma unroll
        for (int j2 = 0; j2 < 2; j2++) { acc1p[i][j2] = 0ull; accgp[i][j2] = 0ull; }

    for (int k0 = 0; k0 < DIN; k0 += 16) {
        {
            int m  = tid >> 2;
            int kq = (tid & 3) << 2;
            float4 v = *(const float4*)(x + (size_t)(row0 + m) * DIN + k0 + kq);
            Xs[kq + 0][m] = v.x; Xs[kq + 1][m] = v.y;
            Xs[kq + 2][m] = v.z; Xs[kq + 3][m] = v.w;
            float4 vr;
            vr.x = __uint_as_float(f2tf32(v.x));
            vr.y = __uint_as_float(f2tf32(v.y));
            vr.z = __uint_as_float(f2tf32(v.z));
            vr.w = __uint_as_float(f2tf32(v.w));
            *(float4*)(g_xt + (size_t)(row0 + m) * DIN + k0 + kq) = vr;
        }
#pragma unroll
        for (int r = 0; r < 2; r++) {
            int lin = tid + r * 256;
            int kk  = lin >> 5;
            int nq  = (lin & 31) << 2;
            *(float4*)&W1s[kk][nq] = *(const float4*)(w1 + (size_t)(k0 + kk) * Hdim + nq);
            *(float4*)&WGs[kk][nq] = *(const float4*)(wg + (size_t)(k0 + kk) * Hdim + nq);
        }
        __syncthreads();
#pragma unroll
        for (int kk = 0; kk < 16; kk++) {
            uint64_t xp[8];
#pragma unroll
            for (int i = 0; i < 8; i++) xp[i] = splat_x2(Xs[kk][i * 8 + ty]);
            uint64_t w1p[2], wgp[2];
#pragma unroll
            for (int j2 = 0; j2 < 2; j2++) {
                w1p[j2] = *(const uint64_t*)&W1s[kk][j2 * 64 + 2 * tx];
                wgp[j2] = *(const uint64_t*)&WGs[kk][j2 * 64 + 2 * tx];
            }
#pragma unroll
            for (int i = 0; i < 8; i++)
#pragma unroll
                for (int j2 = 0; j2 < 2; j2++) {
                    fma_x2(acc1p[i][j2], xp[i], w1p[j2]);
                    fma_x2(accgp[i][j2], xp[i], wgp[j2]);
                }
        }
        __syncthreads();
    }

#pragma unroll
    for (int i = 0; i < 8; i++) {
        int r = i * 8 + ty;
#pragma unroll
        for (int j2 = 0; j2 < 2; j2++) {
            int n = j2 * 64 + 2 * tx;
            uint32_t alo, ahi, glo, ghi;
            asm("mov.b64 {%0, %1}, %2;" : "=r"(alo), "=r"(ahi) : "l"(acc1p[i][j2]));
            asm("mov.b64 {%0, %1}, %2;" : "=r"(glo), "=r"(ghi) : "l"(accgp[i][j2]));
            float a0 = __uint_as_float(alo) + b1[n];
            float a1 = __uint_as_float(ahi) + b1[n + 1];
            float g0 = fmaxf(__uint_as_float(glo) + bg[n],     0.f);
            float g1 = fmaxf(__uint_as_float(ghi) + bg[n + 1], 0.f);
            float2 hv;
            hv.x = fmaxf(a0 * g0, 0.f);
            hv.y = fmaxf(a1 * g1, 0.f);
            *(float2*)&Hs[r][n] = hv;
        }
    }
    for (int i = tid; i < Hdim * Ecnt; i += 256) W2s[i] = w2[i];
    __syncthreads();

    {
        const int r = tid >> 2;
        const int q = tid & 3;
        float acc[Ecnt];
#pragma unroll
        for (int e = 0; e < Ecnt; e++) acc[e] = 0.f;
#pragma unroll 4
        for (int k = 0; k < 32; k++) {
            int n = q * 32 + k;
            float hv = Hs[r][n];
#pragma unroll
            for (int e = 0; e < Ecnt; e++)
                acc[e] = fmaf(hv, W2s[n * Ecnt + e], acc[e]);
        }
#pragma unroll
        for (int e = 0; e < Ecnt; e++) {
            acc[e] += __shfl_xor_sync(0xffffffffu, acc[e], 1);
            acc[e] += __shfl_xor_sync(0xffffffffu, acc[e], 2);
        }
        if (q == 0) {
#pragma unroll
            for (int e = 0; e < Ecnt; e++)
                g_logits[(size_t)(row0 + r) * Ecnt + e] = acc[e] + b2[e];
        }
    }
}

// ---------------------------------------------------------------------------
// Kernel 3: per expert — column softmax, exact top-2048 (radix bisection).
// ---------------------------------------------------------------------------
#define EQ_CAP 1024
__global__ __launch_bounds__(1024) void k_select()
{
    __shared__ float lv[Bsz];
    __shared__ float s_warp[32];
    __shared__ int   s_bits[32];
    __shared__ unsigned s_cnt;
    __shared__ int   s_eq[EQ_CAP];
    __shared__ unsigned s_eqn;
    __shared__ float s_bf;

    const int e    = blockIdx.x;
    const int tid  = threadIdx.x;
    const int lane = tid & 31;
    const int wid  = tid >> 5;

    float loc[8];
#pragma unroll
    for (int r = 0; r < 8; r++) {
        int i = tid * 8 + r;
        loc[r] = g_logits[(size_t)i * Ecnt + e];
        g_sel_slot[i][e] = -1;
    }
    if (tid < 32) s_bits[tid] = 0;
    if (tid == 0) { s_cnt = 0u; s_eqn = 0u; }

    float m = loc[0];
#pragma unroll
    for (int r = 1; r < 8; r++) m = fmaxf(m, loc[r]);
#pragma unroll
    for (int o = 16; o > 0; o >>= 1) m = fmaxf(m, __shfl_xor_sync(0xffffffffu, m, o));
    if (lane == 0) s_warp[wid] = m;
    __syncthreads();
    if (tid < 32) {
        float v = s_warp[tid];
#pragma unroll
        for (int o = 16; o > 0; o >>= 1) v = fmaxf(v, __shfl_xor_sync(0xffffffffu, v, o));
        if (tid == 0) s_bf = v;
    }
    __syncthreads();
    m = s_bf;
    __syncthreads();

    float s = 0.f;
#pragma unroll
    for (int r = 0; r < 8; r++) s += expf(loc[r] - m);
#pragma unroll
    for (int o = 16; o > 0; o >>= 1) s += __shfl_xor_sync(0xffffffffu, s, o);
    if (lane == 0) s_warp[wid] = s;
    __syncthreads();
    if (tid < 32) {
        float v = s_warp[tid];
#pragma unroll
        for (int o = 16; o > 0; o >>= 1) v += __shfl_xor_sync(0xffffffffu, v, o);
        if (tid == 0) s_bf = v;
    }
    __syncthreads();
    s = s_bf;
    __syncthreads();

    const float inv_s = 1.0f / s;
    unsigned ub[8];
#pragma unroll
    for (int r = 0; r < 8; r++) {
        float v = expf(loc[r] - m) * inv_s;
        lv[tid * 8 + r] = v;
        ub[r] = __float_as_uint(v);
    }
    __syncthreads();

    unsigned cur = 0u;
    for (int bit = 29; bit >= 0; bit--) {
        unsigned cand = cur | (1u << bit);
        int c = 0;
#pragma unroll
        for (int r = 0; r < 8; r++) c += (ub[r] >= cand) ? 1 : 0;
#pragma unroll
        for (int o = 16; o > 0; o >>= 1) c += __shfl_xor_sync(0xffffffffu, c, o);
        if (lane == 0) atomicAdd(&s_bits[bit], c);
        __syncthreads();
        if (s_bits[bit] >= BKSEL) cur = cand;
    }
    const unsigned V = cur;

#pragma unroll
    for (int r = 0; r < 8; r++) {
        int i = tid * 8 + r;
        if (ub[r] > V) {
            unsigned p = atomicAdd(&s_cnt, 1u);
            g_idx[e][p] = i;
            g_sel_slot[i][e] = (int)p;
        } else if (ub[r] == V) {
            unsigned q = atomicAdd(&s_eqn, 1u);
            if (q < EQ_CAP) s_eq[q] = i;
        }
    }
    __syncthreads();

    const unsigned n_greater = s_cnt;
    const unsigned needed    = BKSEL - n_greater;
    const unsigned eqn       = s_eqn;

    if (eqn == needed && eqn <= EQ_CAP) {
        for (unsigned q = tid; q < eqn; q += 1024) {
            int i = s_eq[q];
            unsigned p = n_greater + q;
            g_idx[e][p] = i;
            g_sel_slot[i][e] = (int)p;
        }
    } else if (tid == 0) {
        unsigned p = n_greater;
        for (int i = 0; i < Bsz && p < BKSEL; i++) {
            if (__float_as_uint(lv[i]) == V) {
                g_idx[e][p] = i;
                g_sel_slot[i][e] = (int)p;
                p++;
            }
        }
    }
    __syncthreads();

    float wsv[2];
    float m2 = -1e30f;
#pragma unroll
    for (int r = 0; r < 2; r++) {
        int slot = tid + r * 1024;
        wsv[r] = lv[g_idx[e][slot]];
        m2 = fmaxf(m2, wsv[r]);
    }
#pragma unroll
    for (int o = 16; o > 0; o >>= 1) m2 = fmaxf(m2, __shfl_xor_sync(0xffffffffu, m2, o));
    if (lane == 0) s_warp[wid] = m2;
    __syncthreads();
    if (tid < 32) {
        float v = s_warp[tid];
#pragma unroll
        for (int o = 16; o > 0; o >>= 1) v = fmaxf(v, __shfl_xor_sync(0xffffffffu, v, o));
        if (tid == 0) s_bf = v;
    }
    __syncthreads();
    m2 = s_bf;
    __syncthreads();

    float s2 = expf(wsv[0] - m2) + expf(wsv[1] - m2);
#pragma unroll
    for (int o = 16; o > 0; o >>= 1) s2 += __shfl_xor_sync(0xffffffffu, s2, o);
    if (lane == 0) s_warp[wid] = s2;
    __syncthreads();
    if (tid < 32) {
        float v = s_warp[tid];
#pragma unroll
        for (int o = 16; o > 0; o >>= 1) v += __shfl_xor_sync(0xffffffffu, v, o);
        if (tid == 0) s_bf = v;
    }
    __syncthreads();
    s2 = s_bf;

    const float inv_s2 = 1.0f / s2;
#pragma unroll
    for (int r = 0; r < 2; r++)
        g_nws[e][tid + r * 1024] = expf(wsv[r] - m2) * inv_s2;
}

// ---------------------------------------------------------------------------
// Kernel 4: expert GEMM (tf32 mma.sync m16n8k8), R11 shape (128x128 block,
// 8 warps 2m x 4n, warp 64x32, 2 CTA/SM) with ldmatrix fragment loads:
// per k8-step 6 LDSM.x4 instead of 24 LDS.32. A and B tiles both stored as
// 128 rows x 16 k-floats, stride 20 (conflict-free LDSM phases).
// B comes from n-major g_wt so its rows are n-rows.
// ---------------------------------------------------------------------------
#define STRIDE 20
#define STG_FLOATS (128 * STRIDE)       // floats per (A or B) stage
#define SMEM_EXPERT_BYTES (3 * 2 * STG_FLOATS * 4)   // 61440

__global__ __launch_bounds__(256, 2) void k_expert(
    const float* __restrict__ be)
{
    extern __shared__ float smem[];
    __shared__ int ridx[128];

    const int e  = blockIdx.z;
    const int m0 = blockIdx.y * 128;
    const int n0 = blockIdx.x * 128;
    const int tid  = threadIdx.x;
    const int lane = tid & 31;
    const int w    = tid >> 5;
    const int wm   = w & 1;        // warp row (0..1) -> 64 rows
    const int wn   = w >> 1;       // warp col (0..3) -> 32 cols
    const int g    = lane >> 2;    // group id 0..7
    const int c    = lane & 3;     // thread-in-group 0..3

    if (tid < 128) ridx[tid] = g_idx[e][m0 + tid];
    __syncthreads();

    const uint32_t sbase = (uint32_t)__cvta_generic_to_shared(smem);

    // per-lane ldmatrix row addressing (byte offsets within a stage)
    const int lj  = lane >> 3;         // matrix index 0..3
    const int lr  = lane & 7;          // row within matrix
    // A x4: mats {rows+0,k-lo},{rows+8,k-lo},{rows+0,k-hi},{rows+8,k-hi}
    const int rA  = (lj & 1) * 8 + lr;
    const int kA  = (lj >> 1) * 16;    // bytes
    uint32_t aoff[4];
#pragma unroll
    for (int mi = 0; mi < 4; mi++)
        aoff[mi] = (uint32_t)((wm * 64 + mi * 16 + rA) * STRIDE * 4 + kA);
    // B x4: mats {nj,k-lo},{nj,k-hi},{nj+1,k-lo},{nj+1,k-hi}
    const int rB  = (lj >> 1) * 8 + lr;
    const int kB  = (lj & 1) * 16;     // bytes
    uint32_t boff[2];
#pragma unroll
    for (int njp = 0; njp < 2; njp++)
        boff[njp] = (uint32_t)((wn * 32 + njp * 16 + rB) * STRIDE * 4 + kB);

    const float* weE = g_wt + ((size_t)e * DOUT + n0) * DIN;

    float acc[4][4][4];
#pragma unroll
    for (int mi = 0; mi < 4; mi++)
#pragma unroll
        for (int nj = 0; nj < 4; nj++)
#pragma unroll
            for (int q = 0; q < 4; q++) acc[mi][nj][q] = 0.f;

    // stage layout: [stage][A 128x20 | B 128x20]
#define A_BASE(S) (sbase + (S) * 2 * STG_FLOATS * 4)
#define B_BASE(S) (sbase + ((S) * 2 + 1) * STG_FLOATS * 4)

#define LOAD_STAGE(S, k0)                                                      \
    do {                                                                       \
        _Pragma("unroll")                                                      \
        for (int s_ = 0; s_ < 2; s_++) {                                       \
            int lin = tid + s_ * 256;                                          \
            int row = lin >> 2, col = (lin & 3) << 2;                          \
            cp_async16_s(A_BASE(S) + row * (STRIDE * 4) + col * 4,             \
                         g_xt + (size_t)ridx[row] * DIN + (k0) + col);         \
        }                                                                      \
        _Pragma("unroll")                                                      \
        for (int s_ = 0; s_ < 2; s_++) {                                       \
            int lin = tid + s_ * 256;                                          \
            int row = lin >> 2, col = (lin & 3) << 2;                          \
            cp_async16_s(B_BASE(S) + row * (STRIDE * 4) + col * 4,             \
                         weE + (size_t)row * DIN + (k0) + col);                \
        }                                                                      \
        asm volatile("cp.async.commit_group;\n");                              \
    } while (0)

    LOAD_STAGE(0, 0);
    LOAD_STAGE(1, 16);

    const int NT = DIN / 16;   // 64 iterations
    int buf = 0, nbuf = 2;
    for (int t = 0; t < NT; t++) {
        if (t + 2 < NT) {
            asm volatile("cp.async.wait_group 1;\n");
            __syncthreads();
            if (nbuf == 0)      LOAD_STAGE(0, (t + 2) * 16);
            else if (nbuf == 1) LOAD_STAGE(1, (t + 2) * 16);
            else                LOAD_STAGE(2, (t + 2) * 16);
        } else {
            asm volatile("cp.async.wait_group 0;\n");
            __syncthreads();
        }

        const uint32_t aS = A_BASE(buf);
        const uint32_t bS = B_BASE(buf);
#pragma unroll
        for (int kk = 0; kk < 2; kk++) {        // two k8 steps per kb16
            const uint32_t kbyte = (uint32_t)(kk * 8 * 4);
            uint32_t aF[4][4];
            uint32_t bF[4][4];                  // [njp][4 regs]
#pragma unroll
            for (int mi = 0; mi < 4; mi++)
                ldsm_x4(aF[mi], aS + aoff[mi] + kbyte);
#pragma unroll
            for (int njp = 0; njp < 2; njp++)
                ldsm_x4(bF[njp], bS + boff[njp] + kbyte);
            // bF[njp] = {nj=2njp:[0], 2njp:[1], 2njp+1:[0], 2njp+1:[1]}
#pragma unroll
            for (int mi = 0; mi < 4; mi++) {
#pragma unroll
                for (int njp = 0; njp < 2; njp++) {
                    mma_tf32(acc[mi][2 * njp    ], aF[mi], &bF[njp][0]);
                    mma_tf32(acc[mi][2 * njp + 1], aF[mi], &bF[njp][2]);
                }
            }
        }
        buf++;  if (buf == 3)  buf = 0;
        nbuf++; if (nbuf == 3) nbuf = 0;
    }
#undef LOAD_STAGE
#undef A_BASE
#undef B_BASE

    const float* beE = be + (size_t)e * DOUT + n0;
#pragma unroll
    for (int mi = 0; mi < 4; mi++) {
        int slot0 = m0 + wm * 64 + mi * 16 + g;
        int slot1 = slot0 + 8;
        float nw0 = g_nws[e][slot0];
        float nw1 = g_nws[e][slot1];
        float* o0 = g_eo + ((size_t)slot0 * Ecnt + e) * DOUT + n0;
        float* o1 = g_eo + ((size_t)slot1 * Ecnt + e) * DOUT + n0;
#pragma unroll
        for (int nj = 0; nj < 4; nj++) {
            int n = wn * 32 + nj * 8 + c * 2;
            float bb0 = beE[n], bb1 = beE[n + 1];
            float2 v0, v1;
            v0.x = (acc[mi][nj][0] + bb0) * nw0;
            v0.y = (acc[mi][nj][1] + bb1) * nw0;
            v1.x = (acc[mi][nj][2] + bb0) * nw1;
            v1.y = (acc[mi][nj][3] + bb1) * nw1;
            *(float2*)(o0 + n) = v0;
            *(float2*)(o1 + n) = v1;
        }
    }
}

// ---------------------------------------------------------------------------
// Kernel 5: combine (float4). out[b, e*DOUT+d] = c_e[d] + sum_e' c_e'[d]
// ---------------------------------------------------------------------------
__global__ __launch_bounds__(256) void k_combine(float* __restrict__ out)
{
    __shared__ int slots[Ecnt];
    const int b   = blockIdx.x;
    const int tid = threadIdx.x;
    if (tid < Ecnt) slots[tid] = g_sel_slot[b][tid];
    __syncthreads();

    const int d = tid * 4;
    float4 cv[Ecnt];
    float4 ssum = make_float4(0.f, 0.f, 0.f, 0.f);
#pragma unroll
    for (int e = 0; e < Ecnt; e++) {
        int slot = slots[e];
        float4 v = make_float4(0.f, 0.f, 0.f, 0.f);
        if (slot >= 0)
            v = *(const float4*)(g_eo + ((size_t)slot * Ecnt + e) * DOUT + d);
        cv[e] = v;
        ssum.x += v.x; ssum.y += v.y; ssum.z += v.z; ssum.w += v.w;
    }
    float* orow = out + (size_t)b * (Ecnt * DOUT) + d;
#pragma unroll
    for (int e = 0; e < Ecnt; e++) {
        float4 o;
        o.x = cv[e].x + ssum.x;
        o.y = cv[e].y + ssum.y;
        o.z = cv[e].z + ssum.z;
        o.w = cv[e].w + ssum.w;
        *(float4*)(orow + (size_t)e * DOUT) = o;
    }
}

// ---------------------------------------------------------------------------
extern "C" void kernel_launch(void* const* d_in, const int* in_sizes, int n_in,
                              void* d_out, int out_size)
{
    const float* x  = (const float*)d_in[0];
    const float* w1 = (const float*)d_in[1];
    const float* b1 = (const float*)d_in[2];
    const float* wg = (const float*)d_in[3];
    const float* bg = (const float*)d_in[4];
    const float* w2 = (const float*)d_in[5];
    const float* b2 = (const float*)d_in[6];
    const float* we = (const float*)d_in[7];
    const float* be = (const float*)d_in[8];
    float* out = (float*)d_out;

    cudaFuncSetAttribute(k_expert, cudaFuncAttributeMaxDynamicSharedMemorySize,
                         SMEM_EXPERT_BYTES);

    k_cvtw<<<dim3(DOUT / 32, DIN / 32, Ecnt), 256>>>(we);
    k_router<<<Bsz / 64, 256>>>(x, w1, b1, wg, bg, w2, b2);
    k_select<<<Ecnt, 1024>>>();
    k_expert<<<dim3(DOUT / 128, BKSEL / 128, Ecnt), 256, SMEM_EXPERT_BYTES>>>(be);
    k_combine<<<Bsz, 256>>>(out);
}

// round 15
// speedup vs baseline: 1.1777x; 1.0604x over previous
#include <cuda_runtime.h>
#include <math.h>
#include <stdint.h>

#define Bsz   8192
#define DIN   1024
#define Hdim  128
#define Ecnt  8
#define DOUT  1024
#define BKSEL 2048   // ceil(K*B/E) = ceil(2*8192/8)

// ---------------- scratch (device globals; no runtime allocation) ----------
__device__ float g_logits[Bsz * Ecnt];
__device__ int   g_idx[Ecnt][BKSEL];
__device__ float g_nws[Ecnt][BKSEL];
__device__ int   g_sel_slot[Bsz][Ecnt];
__device__ float g_eo[(size_t)BKSEL * Ecnt * DOUT]; // 64 MB [slot][e][d]
__device__ float g_xt[(size_t)Bsz * DIN];           // x, tf32-rounded (by router)
__device__ float g_wt[(size_t)Ecnt * DOUT * DIN];   // we TRANSPOSED [e][n][k], tf32-rounded

// ---------------------------------------------------------------------------
// helpers
// ---------------------------------------------------------------------------
__device__ __forceinline__ void cp_async16_s(uint32_t smem, const void* gmem) {
    asm volatile("cp.async.cg.shared.global [%0], [%1], 16;\n" :: "r"(smem), "l"(gmem));
}
__device__ __forceinline__ uint32_t f2tf32(float v) {
    uint32_t r;
    asm("cvt.rna.tf32.f32 %0, %1;\n" : "=r"(r) : "f"(v));
    return r;
}
__device__ __forceinline__ void mma_tf32(float* cc,
                                         const uint32_t* a, const uint32_t* b) {
    asm volatile(
        "mma.sync.aligned.m16n8k8.row.col.f32.tf32.tf32.f32 "
        "{%0,%1,%2,%3}, {%4,%5,%6,%7}, {%8,%9}, {%0,%1,%2,%3};\n"
        : "+f"(cc[0]), "+f"(cc[1]), "+f"(cc[2]), "+f"(cc[3])
        : "r"(a[0]), "r"(a[1]), "r"(a[2]), "r"(a[3]), "r"(b[0]), "r"(b[1]));
}
__device__ __forceinline__ void ldsm_x4(uint32_t* r, uint32_t saddr) {
    asm volatile("ldmatrix.sync.aligned.m8n8.x4.shared.b16 {%0,%1,%2,%3}, [%4];"
                 : "=r"(r[0]), "=r"(r[1]), "=r"(r[2]), "=r"(r[3]) : "r"(saddr));
}
// packed dual-fp32 FMA (Blackwell FFMA2). Per-lane IEEE fp32 fma.
__device__ __forceinline__ void fma_x2(uint64_t& acc, uint64_t a, uint64_t b) {
    asm("fma.rn.f32x2 %0, %1, %2, %0;" : "+l"(acc) : "l"(a), "l"(b));
}
__device__ __forceinline__ uint64_t splat_x2(float v) {
    uint64_t r;
    uint32_t u = __float_as_uint(v);
    asm("mov.b64 %0, {%1, %1};" : "=l"(r) : "r"(u));
    return r;
}

// ---------------------------------------------------------------------------
// Kernel 1: router fused — h = relu((x@w1+b1) * relu(x@wg+bg)) staged in smem,
// then logits = h @ w2 + b2 in the epilogue. Full fp32 via packed FFMA2.
// Also emits g_xt = tf32-rounded x.
// ---------------------------------------------------------------------------
__global__ __launch_bounds__(256) void k_router(
    const float* __restrict__ x,
    const float* __restrict__ w1, const float* __restrict__ b1,
    const float* __restrict__ wg, const float* __restrict__ bg,
    const float* __restrict__ w2, const float* __restrict__ b2)
{
    __shared__ float Xs[16][64];
    __shared__ float W1s[16][128];
    __shared__ float WGs[16][128];
    __shared__ float Hs[64][132];
    __shared__ float W2s[Hdim * Ecnt];

    const int tid = threadIdx.x;
    const int tx  = tid & 31;
    const int ty  = tid >> 5;
    const int row0 = blockIdx.x * 64;

    uint64_t acc1p[8][2];
    uint64_t accgp[8][2];
#pragma unroll
    for (int i = 0; i < 8; i++)
#pragma unroll
        for (int j2 = 0; j2 < 2; j2++) { acc1p[i][j2] = 0ull; accgp[i][j2] = 0ull; }

    for (int k0 = 0; k0 < DIN; k0 += 16) {
        {
            int m  = tid >> 2;
            int kq = (tid & 3) << 2;
            float4 v = *(const float4*)(x + (size_t)(row0 + m) * DIN + k0 + kq);
            Xs[kq + 0][m] = v.x; Xs[kq + 1][m] = v.y;
            Xs[kq + 2][m] = v.z; Xs[kq + 3][m] = v.w;
            float4 vr;
            vr.x = __uint_as_float(f2tf32(v.x));
            vr.y = __uint_as_float(f2tf32(v.y));
            vr.z = __uint_as_float(f2tf32(v.z));
            vr.w = __uint_as_float(f2tf32(v.w));
            *(float4*)(g_xt + (size_t)(row0 + m) * DIN + k0 + kq) = vr;
        }
#pragma unroll
        for (int r = 0; r < 2; r++) {
            int lin = tid + r * 256;
            int kk  = lin >> 5;
            int nq  = (lin & 31) << 2;
            *(float4*)&W1s[kk][nq] = *(const float4*)(w1 + (size_t)(k0 + kk) * Hdim + nq);
            *(float4*)&WGs[kk][nq] = *(const float4*)(wg + (size_t)(k0 + kk) * Hdim + nq);
        }
        __syncthreads();
#pragma unroll
        for (int kk = 0; kk < 16; kk++) {
            uint64_t xp[8];
#pragma unroll
            for (int i = 0; i < 8; i++) xp[i] = splat_x2(Xs[kk][i * 8 + ty]);
            uint64_t w1p[2], wgp[2];
#pragma unroll
            for (int j2 = 0; j2 < 2; j2++) {
                w1p[j2] = *(const uint64_t*)&W1s[kk][j2 * 64 + 2 * tx];
                wgp[j2] = *(const uint64_t*)&WGs[kk][j2 * 64 + 2 * tx];
            }
#pragma unroll
            for (int i = 0; i < 8; i++)
#pragma unroll
                for (int j2 = 0; j2 < 2; j2++) {
                    fma_x2(acc1p[i][j2], xp[i], w1p[j2]);
                    fma_x2(accgp[i][j2], xp[i], wgp[j2]);
                }
        }
        __syncthreads();
    }

#pragma unroll
    for (int i = 0; i < 8; i++) {
        int r = i * 8 + ty;
#pragma unroll
        for (int j2 = 0; j2 < 2; j2++) {
            int n = j2 * 64 + 2 * tx;
            uint32_t alo, ahi, glo, ghi;
            asm("mov.b64 {%0, %1}, %2;" : "=r"(alo), "=r"(ahi) : "l"(acc1p[i][j2]));
            asm("mov.b64 {%0, %1}, %2;" : "=r"(glo), "=r"(ghi) : "l"(accgp[i][j2]));
            float a0 = __uint_as_float(alo) + b1[n];
            float a1 = __uint_as_float(ahi) + b1[n + 1];
            float g0 = fmaxf(__uint_as_float(glo) + bg[n],     0.f);
            float g1 = fmaxf(__uint_as_float(ghi) + bg[n + 1], 0.f);
            float2 hv;
            hv.x = fmaxf(a0 * g0, 0.f);
            hv.y = fmaxf(a1 * g1, 0.f);
            *(float2*)&Hs[r][n] = hv;
        }
    }
    for (int i = tid; i < Hdim * Ecnt; i += 256) W2s[i] = w2[i];
    __syncthreads();

    {
        const int r = tid >> 2;
        const int q = tid & 3;
        float acc[Ecnt];
#pragma unroll
        for (int e = 0; e < Ecnt; e++) acc[e] = 0.f;
#pragma unroll 4
        for (int k = 0; k < 32; k++) {
            int n = q * 32 + k;
            float hv = Hs[r][n];
#pragma unroll
            for (int e = 0; e < Ecnt; e++)
                acc[e] = fmaf(hv, W2s[n * Ecnt + e], acc[e]);
        }
#pragma unroll
        for (int e = 0; e < Ecnt; e++) {
            acc[e] += __shfl_xor_sync(0xffffffffu, acc[e], 1);
            acc[e] += __shfl_xor_sync(0xffffffffu, acc[e], 2);
        }
        if (q == 0) {
#pragma unroll
            for (int e = 0; e < Ecnt; e++)
                g_logits[(size_t)(row0 + r) * Ecnt + e] = acc[e] + b2[e];
        }
    }
}

// ---------------------------------------------------------------------------
// Kernel 3: fused select + we-transpose.
// Blocks 0..7: per-expert column softmax + exact top-2048 (radix bisection).
// Blocks 8.. : transpose we [e][k][n] -> g_wt [e][n][k] with tf32 rounding
// (fills the 140 SMs that plain select leaves idle).
// ---------------------------------------------------------------------------
#define EQ_CAP 1024
__global__ __launch_bounds__(1024) void k_selectx(const float* __restrict__ we)
{
    __shared__ float lv[Bsz];
    __shared__ float s_warp[32];
    __shared__ int   s_bits[32];
    __shared__ unsigned s_cnt;
    __shared__ int   s_eq[EQ_CAP];
    __shared__ unsigned s_eqn;
    __shared__ float s_bf;
    __shared__ float tile[32][33];

    const int tid  = threadIdx.x;

    if (blockIdx.x >= Ecnt) {
        // ---- transpose tile: 32x32, 1024 threads, 1 element each ----
        const int t  = blockIdx.x - Ecnt;
        const int e  = t >> 10;              // 1024 tiles per expert
        const int rem = t & 1023;
        const int k0 = (rem >> 5) * 32;
        const int n0 = (rem & 31) * 32;
        const int r  = tid >> 5;             // 0..31
        const int c  = tid & 31;

        const float* src = we + ((size_t)e * DIN + k0) * DOUT + n0;
        tile[r][c] = __uint_as_float(f2tf32(src[(size_t)r * DOUT + c]));
        __syncthreads();
        float* dst = g_wt + ((size_t)e * DOUT + n0) * DIN + k0;
        dst[(size_t)r * DIN + c] = tile[c][r];
        return;
    }

    const int e    = blockIdx.x;
    const int lane = tid & 31;
    const int wid  = tid >> 5;

    float loc[8];
#pragma unroll
    for (int r = 0; r < 8; r++) {
        int i = tid * 8 + r;
        loc[r] = g_logits[(size_t)i * Ecnt + e];
        g_sel_slot[i][e] = -1;
    }
    if (tid < 32) s_bits[tid] = 0;
    if (tid == 0) { s_cnt = 0u; s_eqn = 0u; }

    float m = loc[0];
#pragma unroll
    for (int r = 1; r < 8; r++) m = fmaxf(m, loc[r]);
#pragma unroll
    for (int o = 16; o > 0; o >>= 1) m = fmaxf(m, __shfl_xor_sync(0xffffffffu, m, o));
    if (lane == 0) s_warp[wid] = m;
    __syncthreads();
    if (tid < 32) {
        float v = s_warp[tid];
#pragma unroll
        for (int o = 16; o > 0; o >>= 1) v = fmaxf(v, __shfl_xor_sync(0xffffffffu, v, o));
        if (tid == 0) s_bf = v;
    }
    __syncthreads();
    m = s_bf;
    __syncthreads();

    float s = 0.f;
#pragma unroll
    for (int r = 0; r < 8; r++) s += expf(loc[r] - m);
#pragma unroll
    for (int o = 16; o > 0; o >>= 1) s += __shfl_xor_sync(0xffffffffu, s, o);
    if (lane == 0) s_warp[wid] = s;
    __syncthreads();
    if (tid < 32) {
        float v = s_warp[tid];
#pragma unroll
        for (int o = 16; o > 0; o >>= 1) v += __shfl_xor_sync(0xffffffffu, v, o);
        if (tid == 0) s_bf = v;
    }
    __syncthreads();
    s = s_bf;
    __syncthreads();

    const float inv_s = 1.0f / s;
    unsigned ub[8];
#pragma unroll
    for (int r = 0; r < 8; r++) {
        float v = expf(loc[r] - m) * inv_s;
        lv[tid * 8 + r] = v;
        ub[r] = __float_as_uint(v);
    }
    __syncthreads();

    unsigned cur = 0u;
    for (int bit = 29; bit >= 0; bit--) {
        unsigned cand = cur | (1u << bit);
        int c = 0;
#pragma unroll
        for (int r = 0; r < 8; r++) c += (ub[r] >= cand) ? 1 : 0;
#pragma unroll
        for (int o = 16; o > 0; o >>= 1) c += __shfl_xor_sync(0xffffffffu, c, o);
        if (lane == 0) atomicAdd(&s_bits[bit], c);
        __syncthreads();
        if (s_bits[bit] >= BKSEL) cur = cand;
    }
    const unsigned V = cur;

#pragma unroll
    for (int r = 0; r < 8; r++) {
        int i = tid * 8 + r;
        if (ub[r] > V) {
            unsigned p = atomicAdd(&s_cnt, 1u);
            g_idx[e][p] = i;
            g_sel_slot[i][e] = (int)p;
        } else if (ub[r] == V) {
            unsigned q = atomicAdd(&s_eqn, 1u);
            if (q < EQ_CAP) s_eq[q] = i;
        }
    }
    __syncthreads();

    const unsigned n_greater = s_cnt;
    const unsigned needed    = BKSEL - n_greater;
    const unsigned eqn       = s_eqn;

    if (eqn == needed && eqn <= EQ_CAP) {
        for (unsigned q = tid; q < eqn; q += 1024) {
            int i = s_eq[q];
            unsigned p = n_greater + q;
            g_idx[e][p] = i;
            g_sel_slot[i][e] = (int)p;
        }
    } else if (tid == 0) {
        unsigned p = n_greater;
        for (int i = 0; i < Bsz && p < BKSEL; i++) {
            if (__float_as_uint(lv[i]) == V) {
                g_idx[e][p] = i;
                g_sel_slot[i][e] = (int)p;
                p++;
            }
        }
    }
    __syncthreads();

    float wsv[2];
    float m2 = -1e30f;
#pragma unroll
    for (int r = 0; r < 2; r++) {
        int slot = tid + r * 1024;
        wsv[r] = lv[g_idx[e][slot]];
        m2 = fmaxf(m2, wsv[r]);
    }
#pragma unroll
    for (int o = 16; o > 0; o >>= 1) m2 = fmaxf(m2, __shfl_xor_sync(0xffffffffu, m2, o));
    if (lane == 0) s_warp[wid] = m2;
    __syncthreads();
    if (tid < 32) {
        float v = s_warp[tid];
#pragma unroll
        for (int o = 16; o > 0; o >>= 1) v = fmaxf(v, __shfl_xor_sync(0xffffffffu, v, o));
        if (tid == 0) s_bf = v;
    }
    __syncthreads();
    m2 = s_bf;
    __syncthreads();

    float s2 = expf(wsv[0] - m2) + expf(wsv[1] - m2);
#pragma unroll
    for (int o = 16; o > 0; o >>= 1) s2 += __shfl_xor_sync(0xffffffffu, s2, o);
    if (lane == 0) s_warp[wid] = s2;
    __syncthreads();
    if (tid < 32) {
        float v = s_warp[tid];
#pragma unroll
        for (int o = 16; o > 0; o >>= 1) v += __shfl_xor_sync(0xffffffffu, v, o);
        if (tid == 0) s_bf = v;
    }
    __syncthreads();
    s2 = s_bf;

    const float inv_s2 = 1.0f / s2;
#pragma unroll
    for (int r = 0; r < 2; r++)
        g_nws[e][tid + r * 1024] = expf(wsv[r] - m2) * inv_s2;
}

// ---------------------------------------------------------------------------
// Kernel 4: expert GEMM (tf32 mma.sync m16n8k8), 128x128 block, 8 warps
// (2m x 4n, warp 64x32), 2 CTA/SM, ldmatrix fragment loads.
// kb=32 per stage (3 stages, stride 36): half the barriers of kb=16 and
// double the prefetch distance. smem 108 KB/CTA.
// ---------------------------------------------------------------------------
#define STRIDE 36
#define STG_FLOATS (128 * STRIDE)       // floats per (A or B) stage
#define SMEM_EXPERT_BYTES (3 * 2 * STG_FLOATS * 4)   // 110592

__global__ __launch_bounds__(256, 2) void k_expert(
    const float* __restrict__ be)
{
    extern __shared__ float smem[];
    __shared__ int ridx[128];

    const int e  = blockIdx.z;
    const int m0 = blockIdx.y * 128;
    const int n0 = blockIdx.x * 128;
    const int tid  = threadIdx.x;
    const int lane = tid & 31;
    const int w    = tid >> 5;
    const int wm   = w & 1;        // warp row (0..1) -> 64 rows
    const int wn   = w >> 1;       // warp col (0..3) -> 32 cols
    const int g    = lane >> 2;    // group id 0..7
    const int c    = lane & 3;     // thread-in-group 0..3

    if (tid < 128) ridx[tid] = g_idx[e][m0 + tid];
    __syncthreads();

    const uint32_t sbase = (uint32_t)__cvta_generic_to_shared(smem);

    // per-lane ldmatrix row addressing (byte offsets within a stage)
    const int lj  = lane >> 3;         // matrix index 0..3
    const int lr  = lane & 7;          // row within matrix
    // A x4: mats {rows+0,k-lo},{rows+8,k-lo},{rows+0,k-hi},{rows+8,k-hi}
    const int rA  = (lj & 1) * 8 + lr;
    const int kA  = (lj >> 1) * 16;    // bytes
    uint32_t aoff[4];
#pragma unroll
    for (int mi = 0; mi < 4; mi++)
        aoff[mi] = (uint32_t)((wm * 64 + mi * 16 + rA) * STRIDE * 4 + kA);
    // B x4: mats {nj,k-lo},{nj,k-hi},{nj+1,k-lo},{nj+1,k-hi}
    const int rB  = (lj >> 1) * 8 + lr;
    const int kB  = (lj & 1) * 16;     // bytes
    uint32_t boff[2];
#pragma unroll
    for (int njp = 0; njp < 2; njp++)
        boff[njp] = (uint32_t)((wn * 32 + njp * 16 + rB) * STRIDE * 4 + kB);

    const float* weE = g_wt + ((size_t)e * DOUT + n0) * DIN;

    float acc[4][4][4];
#pragma unroll
    for (int mi = 0; mi < 4; mi++)
#pragma unroll
        for (int nj = 0; nj < 4; nj++)
#pragma unroll
            for (int q = 0; q < 4; q++) acc[mi][nj][q] = 0.f;

    // stage layout: [stage][A 128x36 | B 128x36]
#define A_BASE(S) (sbase + (S) * 2 * STG_FLOATS * 4)
#define B_BASE(S) (sbase + ((S) * 2 + 1) * STG_FLOATS * 4)

    // A tile: 128 rows x 32 floats = 1024 f4 -> 4/thread; B same.
#define LOAD_STAGE(S, k0)                                                      \
    do {                                                                       \
        _Pragma("unroll")                                                      \
        for (int s_ = 0; s_ < 4; s_++) {                                       \
            int lin = tid + s_ * 256;                                          \
            int row = lin >> 3, col = (lin & 7) << 2;                          \
            cp_async16_s(A_BASE(S) + row * (STRIDE * 4) + col * 4,             \
                         g_xt + (size_t)ridx[row] * DIN + (k0) + col);         \
        }                                                                      \
        _Pragma("unroll")                                                      \
        for (int s_ = 0; s_ < 4; s_++) {                                       \
            int lin = tid + s_ * 256;                                          \
            int row = lin >> 3, col = (lin & 7) << 2;                          \
            cp_async16_s(B_BASE(S) + row * (STRIDE * 4) + col * 4,             \
                         weE + (size_t)row * DIN + (k0) + col);                \
        }                                                                      \
        asm volatile("cp.async.commit_group;\n");                              \
    } while (0)

    LOAD_STAGE(0, 0);
    LOAD_STAGE(1, 32);

    const int NT = DIN / 32;   // 32 iterations
    int buf = 0, nbuf = 2;
    for (int t = 0; t < NT; t++) {
        if (t + 2 < NT) {
            asm volatile("cp.async.wait_group 1;\n");
            __syncthreads();
            if (nbuf == 0)      LOAD_STAGE(0, (t + 2) * 32);
            else if (nbuf == 1) LOAD_STAGE(1, (t + 2) * 32);
            else                LOAD_STAGE(2, (t + 2) * 32);
        } else {
            asm volatile("cp.async.wait_group 0;\n");
            __syncthreads();
        }

        const uint32_t aS = A_BASE(buf);
        const uint32_t bS = B_BASE(buf);
#pragma unroll
        for (int kk = 0; kk < 4; kk++) {        // four k8 steps per kb32
            const uint32_t kbyte = (uint32_t)(kk * 8 * 4);
            uint32_t aF[4][4];
            uint32_t bF[4][4];                  // [njp][4 regs]
#pragma unroll
            for (int mi = 0; mi < 4; mi++)
                ldsm_x4(aF[mi], aS + aoff[mi] + kbyte);
#pragma unroll
            for (int njp = 0; njp < 2; njp++)
                ldsm_x4(bF[njp], bS + boff[njp] + kbyte);
            // bF[njp] = {nj=2njp:[0], 2njp:[1], 2njp+1:[0], 2njp+1:[1]}
#pragma unroll
            for (int mi = 0; mi < 4; mi++) {
#pragma unroll
                for (int njp = 0; njp < 2; njp++) {
                    mma_tf32(acc[mi][2 * njp    ], aF[mi], &bF[njp][0]);
                    mma_tf32(acc[mi][2 * njp + 1], aF[mi], &bF[njp][2]);
                }
            }
        }
        buf++;  if (buf == 3)  buf = 0;
        nbuf++; if (nbuf == 3) nbuf = 0;
    }
#undef LOAD_STAGE
#undef A_BASE
#undef B_BASE

    const float* beE = be + (size_t)e * DOUT + n0;
#pragma unroll
    for (int mi = 0; mi < 4; mi++) {
        int slot0 = m0 + wm * 64 + mi * 16 + g;
        int slot1 = slot0 + 8;
        float nw0 = g_nws[e][slot0];
        float nw1 = g_nws[e][slot1];
        float* o0 = g_eo + ((size_t)slot0 * Ecnt + e) * DOUT + n0;
        float* o1 = g_eo + ((size_t)slot1 * Ecnt + e) * DOUT + n0;
#pragma unroll
        for (int nj = 0; nj < 4; nj++) {
            int n = wn * 32 + nj * 8 + c * 2;
            float bb0 = beE[n], bb1 = beE[n + 1];
            float2 v0, v1;
            v0.x = (acc[mi][nj][0] + bb0) * nw0;
            v0.y = (acc[mi][nj][1] + bb1) * nw0;
            v1.x = (acc[mi][nj][2] + bb0) * nw1;
            v1.y = (acc[mi][nj][3] + bb1) * nw1;
            *(float2*)(o0 + n) = v0;
            *(float2*)(o1 + n) = v1;
        }
    }
}

// ---------------------------------------------------------------------------
// Kernel 5: combine (float4). out[b, e*DOUT+d] = c_e[d] + sum_e' c_e'[d]
// ---------------------------------------------------------------------------
__global__ __launch_bounds__(256) void k_combine(float* __restrict__ out)
{
    __shared__ int slots[Ecnt];
    const int b   = blockIdx.x;
    const int tid = threadIdx.x;
    if (tid < Ecnt) slots[tid] = g_sel_slot[b][tid];
    __syncthreads();

    const int d = tid * 4;
    float4 cv[Ecnt];
    float4 ssum = make_float4(0.f, 0.f, 0.f, 0.f);
#pragma unroll
    for (int e = 0; e < Ecnt; e++) {
        int slot = slots[e];
        float4 v = make_float4(0.f, 0.f, 0.f, 0.f);
        if (slot >= 0)
            v = *(const float4*)(g_eo + ((size_t)slot * Ecnt + e) * DOUT + d);
        cv[e] = v;
        ssum.x += v.x; ssum.y += v.y; ssum.z += v.z; ssum.w += v.w;
    }
    float* orow = out + (size_t)b * (Ecnt * DOUT) + d;
#pragma unroll
    for (int e = 0; e < Ecnt; e++) {
        float4 o;
        o.x = cv[e].x + ssum.x;
        o.y = cv[e].y + ssum.y;
        o.z = cv[e].z + ssum.z;
        o.w = cv[e].w + ssum.w;
        *(float4*)(orow + (size_t)e * DOUT) = o;
    }
}

// ---------------------------------------------------------------------------
extern "C" void kernel_launch(void* const* d_in, const int* in_sizes, int n_in,
                              void* d_out, int out_size)
{
    const float* x  = (const float*)d_in[0];
    const float* w1 = (const float*)d_in[1];
    const float* b1 = (const float*)d_in[2];
    const float* wg = (const float*)d_in[3];
    const float* bg = (const float*)d_in[4];
    const float* w2 = (const float*)d_in[5];
    const float* b2 = (const float*)d_in[6];
    const float* we = (const float*)d_in[7];
    const float* be = (const float*)d_in[8];
    float* out = (float*)d_out;

    cudaFuncSetAttribute(k_expert, cudaFuncAttributeMaxDynamicSharedMemorySize,
                         SMEM_EXPERT_BYTES);

    k_router<<<Bsz / 64, 256>>>(x, w1, b1, wg, bg, w2, b2);
    // select (8 blocks) + we-transpose (8192 blocks) fused in one launch
    k_selectx<<<Ecnt + Ecnt * (DIN / 32) * (DOUT / 32), 1024>>>(we);
    k_expert<<<dim3(DOUT / 128, BKSEL / 128, Ecnt), 256, SMEM_EXPERT_BYTES>>>(be);
    k_combine<<<Bsz, 256>>>(out);
}